// round 7
// baseline (speedup 1.0000x reference)
#include <cuda_runtime.h>

#define NS   1024
#define XD   128
#define HID  256

typedef unsigned long long u64;
union F2 { u64 u; float f[2]; };

// Scratch (device globals — no allocation allowed)
__device__ float g_px_t[HID * NS];       // pre_x transposed: [k][j]
__device__ u64   g_pyd[HID * NS];        // (pre_y + b1) transposed, duplicated (v,v): [k][i]
__device__ u64   g_w2p[HID];             // W2 packed (w,w)
__device__ float g_sum_exp;
__device__ float g_sum_diag;
__device__ unsigned g_done;

__device__ __forceinline__ u64 pack2(float lo, float hi) {
    u64 r; asm("mov.b64 %0, {%1, %2};" : "=l"(r) : "f"(lo), "f"(hi)); return r;
}
__device__ __forceinline__ u64 add2(u64 a, u64 b) {
    u64 r; asm("add.rn.f32x2 %0, %1, %2;" : "=l"(r) : "l"(a), "l"(b)); return r;
}
__device__ __forceinline__ u64 fma2(u64 a, u64 b, u64 c) {
    u64 r; asm("fma.rn.f32x2 %0, %1, %2, %3;" : "=l"(r) : "l"(a), "l"(b), "l"(c)); return r;
}
__device__ __forceinline__ u64 relu2(u64 a) {
    F2 v; v.u = a;
    v.f[0] = fmaxf(v.f[0], 0.0f);
    v.f[1] = fmaxf(v.f[1], 0.0f);
    return v.u;
}
__device__ __forceinline__ void cpa16(void* smem, const void* gmem) {
    unsigned s = (unsigned)__cvta_generic_to_shared(smem);
    asm volatile("cp.async.cg.shared.global [%0], [%1], 16;" :: "r"(s), "l"(gmem));
}
__device__ __forceinline__ void cpa_commit() {
    asm volatile("cp.async.commit_group;");
}
template <int N>
__device__ __forceinline__ void cpa_wait() {
    asm volatile("cp.async.wait_group %0;" :: "n"(N));
}

// ---------------------------------------------------------------------------
// Kernel 1: pre_x = x @ W1[:128] (bz=0) -> float [k][j]
//           pre_yb = y @ W1[128:] + b1 (bz=1) -> u64 (v,v) [k][i]
// Also zeroes accumulators and pre-packs W2.
// grid (HID/64, NS/64, 2), block (16,16). 64x64 tile, 4x4 micro, f32x2 packed.
// ---------------------------------------------------------------------------
__global__ void gemm_pre_kernel(const float* __restrict__ x,
                                const float* __restrict__ y,
                                const float* __restrict__ W1,
                                const float* __restrict__ b1,
                                const float* __restrict__ W2) {
    const int bz = blockIdx.z;
    const float* __restrict__ A = bz ? y : x;
    const float* __restrict__ W = W1 + (bz ? (XD * HID) : 0);

    __shared__ float As[16][64];   // [k][n]
    __shared__ float Bs[16][64];   // [k][h]

    const int tx = threadIdx.x, ty = threadIdx.y;
    const int tid = ty * 16 + tx;
    const int n0 = blockIdx.y * 64;
    const int h0 = blockIdx.x * 64;

    if (blockIdx.x == 0 && blockIdx.y == 0 && bz == 0) {
        if (tid == 0) { g_sum_exp = 0.0f; g_sum_diag = 0.0f; }
        float w = W2[tid];                 // 256 threads == HID
        g_w2p[tid] = pack2(w, w);
    }

    u64 acc[4][2];
#pragma unroll
    for (int a = 0; a < 4; a++) { acc[a][0] = 0ull; acc[a][1] = 0ull; }

    for (int kk = 0; kk < XD; kk += 16) {
        {
            int m  = tid >> 2;
            int k4 = (tid & 3) * 4;
            float4 v = *(const float4*)&A[(n0 + m) * XD + kk + k4];
            As[k4 + 0][m] = v.x;
            As[k4 + 1][m] = v.y;
            As[k4 + 2][m] = v.z;
            As[k4 + 3][m] = v.w;
        }
#pragma unroll
        for (int t = 0; t < 4; t++) {
            int e = tid + t * 256;
            int h = e & 63;
            int k = e >> 6;
            Bs[k][h] = W[(kk + k) * HID + h0 + h];
        }
        __syncthreads();

#pragma unroll
        for (int k = 0; k < 16; k++) {
            float4 av = *(const float4*)&As[k][ty * 4];
            ulonglong2 bv = *(const ulonglong2*)&Bs[k][tx * 4];
            float aa[4] = {av.x, av.y, av.z, av.w};
#pragma unroll
            for (int a = 0; a < 4; a++) {
                u64 ap = pack2(aa[a], aa[a]);
                acc[a][0] = fma2(ap, bv.x, acc[a][0]);
                acc[a][1] = fma2(ap, bv.y, acc[a][1]);
            }
        }
        __syncthreads();
    }

    // Store: acc[a][*] holds hid = h0+tx*4+{0..3} for n = n0+ty*4+a.
    if (bz == 0) {
#pragma unroll
        for (int b = 0; b < 4; b++) {
            int h = h0 + tx * 4 + b;
            F2 p0, p1, p2, p3;
            p0.u = acc[0][b >> 1]; p1.u = acc[1][b >> 1];
            p2.u = acc[2][b >> 1]; p3.u = acc[3][b >> 1];
            int hl = b & 1;
            float4 v = make_float4(p0.f[hl], p1.f[hl], p2.f[hl], p3.f[hl]);
            *(float4*)&g_px_t[h * NS + n0 + ty * 4] = v;
        }
    } else {
#pragma unroll
        for (int b = 0; b < 4; b++) {
            int h = h0 + tx * 4 + b;
            float bias = b1[h];
            int hl = b & 1;
            u64 vals[4];
#pragma unroll
            for (int a = 0; a < 4; a++) {
                F2 p; p.u = acc[a][b >> 1];
                float v = p.f[hl] + bias;
                vals[a] = pack2(v, v);
            }
            ulonglong2* dst = (ulonglong2*)&g_pyd[h * NS + n0 + ty * 4];
            dst[0] = make_ulonglong2(vals[0], vals[1]);
            dst[1] = make_ulonglong2(vals[2], vals[3]);
        }
    }
}

// ---------------------------------------------------------------------------
// Kernel 2: fused pairwise T1 + exp-sum + diag-sum + (last block) finalize.
// grid (16,16), block 256. Tile 64 i x 64 j, micro 4i x 4j (2 f32x2 pairs).
// Double-buffered tiles via cp.async: next k-chunk loads overlap compute.
// Inner loop has NO packs: Ys pre-duplicated u64, Xs adjacent-float u64 pairs,
// W2 pre-packed.
// ---------------------------------------------------------------------------
__global__ void __launch_bounds__(256)
pairwise_kernel(const float* __restrict__ b2, float* __restrict__ out) {
    __shared__ u64   Ys[2][32][64];   // [buf][k][i]  (v,v) pairs   32KB
    __shared__ float Xs[2][32][64];   // [buf][k][j]                16KB
    __shared__ u64   w2s[HID];        //                             2KB
    __shared__ float r1[8], r2[8];
    __shared__ bool  is_last;

    const int t  = threadIdx.x;        // 0..255
    const int gi = t >> 4;             // 0..15
    const int gj = t & 15;             // 0..15
    const int bi = blockIdx.y * 64;
    const int bj = blockIdx.x * 64;

    w2s[t] = g_w2p[t];                 // 256 == HID

    // Per-thread load coordinates (fixed across chunks).
    const int yk  = t >> 5;            // 0..7   (Ys: 4 rows per thread, stride 8)
    const int yc2 = (t & 31) * 2;      // u64 col
    const int xk  = t >> 4;            // 0..15  (Xs: 2 rows per thread, stride 16)
    const int xc4 = (t & 15) * 4;      // float col

    // Stage loader: chunk kk -> buffer b.
    auto load_stage = [&](int buf, int kk) {
#pragma unroll
        for (int r = 0; r < 4; r++) {
            int k = yk + r * 8;
            cpa16(&Ys[buf][k][yc2], &g_pyd[(kk + k) * NS + bi + yc2]);
        }
#pragma unroll
        for (int r = 0; r < 2; r++) {
            int k = xk + r * 16;
            cpa16(&Xs[buf][k][xc4], &g_px_t[(kk + k) * NS + bj + xc4]);
        }
        cpa_commit();
    };

    u64 acc[4][2];
#pragma unroll
    for (int a = 0; a < 4; a++) { acc[a][0] = 0ull; acc[a][1] = 0ull; }

    load_stage(0, 0);

    const int NCHUNK = HID / 32;       // 8
    for (int it = 0; it < NCHUNK; it++) {
        const int cur = it & 1;
        if (it + 1 < NCHUNK) {
            load_stage(cur ^ 1, (it + 1) * 32);
            cpa_wait<1>();
        } else {
            cpa_wait<0>();
        }
        __syncthreads();

        const int kk = it * 32;
#pragma unroll 8
        for (int k = 0; k < 32; k++) {
            ulonglong2 ya = *(const ulonglong2*)&Ys[cur][k][gi * 4];
            ulonglong2 yb = *(const ulonglong2*)&Ys[cur][k][gi * 4 + 2];
            ulonglong2 xv = *(const ulonglong2*)&Xs[cur][k][gj * 4];
            u64 w = w2s[kk + k];
            u64 yp[4] = {ya.x, ya.y, yb.x, yb.y};
            u64 xp[2] = {xv.x, xv.y};
#pragma unroll
            for (int a = 0; a < 4; a++)
#pragma unroll
                for (int p = 0; p < 2; p++) {
                    u64 s = relu2(add2(yp[a], xp[p]));
                    acc[a][p] = fma2(s, w, acc[a][p]);
                }
        }
        __syncthreads();
    }

    const float c = b2[0] - 1.0f;
    float sexp = 0.0f, sdiag = 0.0f;

#pragma unroll
    for (int a = 0; a < 4; a++)
#pragma unroll
        for (int p = 0; p < 2; p++) {
            F2 v; v.u = acc[a][p];
            sexp += __expf(v.f[0] + c) + __expf(v.f[1] + c);
        }

    // Diagonal: only on diagonal blocks, threads with gi == gj.
    if (bi == bj && gi == gj) {
#pragma unroll
        for (int a = 0; a < 4; a++) {
            F2 v; v.u = acc[a][a >> 1];
            sdiag += v.f[a & 1] + c;
        }
    }

    // Block reduction: 8 warps.
    const int lane = t & 31, wid = t >> 5;
#pragma unroll
    for (int o = 16; o > 0; o >>= 1) {
        sexp  += __shfl_down_sync(0xFFFFFFFFu, sexp,  o);
        sdiag += __shfl_down_sync(0xFFFFFFFFu, sdiag, o);
    }
    if (lane == 0) { r1[wid] = sexp; r2[wid] = sdiag; }
    __syncthreads();
    if (t == 0) {
        float s1 = 0.0f, s2 = 0.0f;
#pragma unroll
        for (int w = 0; w < 8; w++) { s1 += r1[w]; s2 += r2[w]; }
        atomicAdd(&g_sum_exp,  s1);
        atomicAdd(&g_sum_diag, s2);
        __threadfence();
        unsigned v = atomicAdd(&g_done, 1u);
        is_last = (v == gridDim.x * gridDim.y - 1);
    }
    __syncthreads();

    if (is_last && t == 0) {
        g_done = 0;
        __threadfence();
        float n = (float)NS;
        out[0] = (g_sum_diag + n) / n - g_sum_exp / (n * n);
    }
}

// ---------------------------------------------------------------------------
extern "C" void kernel_launch(void* const* d_in, const int* in_sizes, int n_in,
                              void* d_out, int out_size) {
    const float* x  = (const float*)d_in[0];
    const float* y  = (const float*)d_in[1];
    const float* W1 = (const float*)d_in[2];
    const float* b1 = (const float*)d_in[3];
    const float* W2 = (const float*)d_in[4];
    const float* b2 = (const float*)d_in[5];
    float* out = (float*)d_out;

    dim3 blk1(16, 16);
    dim3 g1(HID / 64, NS / 64, 2);
    gemm_pre_kernel<<<g1, blk1>>>(x, y, W1, b1, W2);

    dim3 g2(NS / 64, NS / 64);
    pairwise_kernel<<<g2, 256>>>(b2, out);
}